// round 1
// baseline (speedup 1.0000x reference)
#include <cuda_runtime.h>
#include <math.h>

#define N_NODES 50000
#define DIM     512
#define NOUT    40
#define EMAX    800000

// ---------------- scratch (static device globals: allocation-free) ----------------
__device__ float g_tmp[(size_t)N_NODES * DIM];
__device__ float g_agg[(size_t)N_NODES * DIM];
__device__ float g_x1 [(size_t)N_NODES * DIM];
__device__ float g_x2 [(size_t)N_NODES * DIM];
__device__ float g_x3 [(size_t)N_NODES * DIM];
__device__ int   g_deg[N_NODES];
__device__ float g_dis[N_NODES];
__device__ int   g_rowptr[N_NODES + 1];
__device__ int   g_cursor[N_NODES];
__device__ int   g_col[EMAX];
__device__ float g_sum[DIM];
__device__ float g_sumsq[DIM];
__device__ float g_scale[DIM];
__device__ float g_shift[DIM];

// ---------------- packed f32x2 helpers (2x fp32 FMA throughput on sm_100) ----------
__device__ __forceinline__ void fma2(unsigned long long& c, unsigned long long a,
                                     unsigned long long b) {
    asm("fma.rn.f32x2 %0, %1, %2, %3;" : "=l"(c) : "l"(a), "l"(b), "l"(c));
}
__device__ __forceinline__ unsigned long long dup2(float x) {
    unsigned long long r;
    asm("mov.b64 %0, {%1, %1};" : "=l"(r) : "f"(x));
    return r;
}
__device__ __forceinline__ float2 unpack2(unsigned long long v) {
    float2 r;
    asm("mov.b64 {%0, %1}, %2;" : "=f"(r.x), "=f"(r.y) : "l"(v));
    return r;
}

// ---------------- graph preprocessing -------------------------------------------
__global__ void k_init() {
    int i = blockIdx.x * blockDim.x + threadIdx.x;
    if (i < N_NODES) { g_deg[i] = 1; g_cursor[i] = 0; }   // self-loop counts 1
}

__global__ void k_deg(const int* __restrict__ dst, int E) {
    int e = blockIdx.x * blockDim.x + threadIdx.x;
    if (e < E) atomicAdd(&g_deg[dst[e]], 1);
}

__global__ void k_dis() {
    int i = blockIdx.x * blockDim.x + threadIdx.x;
    if (i < N_NODES) g_dis[i] = rsqrtf((float)g_deg[i]);
}

// single-block scan of edge counts (deg-1) -> row_ptr
__global__ void k_scan() {
    __shared__ int sh[1024];
    int tid = threadIdx.x;
    const int per = (N_NODES + 1023) / 1024;     // 49
    int start = tid * per;
    int stop  = min(start + per, N_NODES);
    int s = 0;
    for (int i = start; i < stop; i++) s += g_deg[i] - 1;
    sh[tid] = s;
    __syncthreads();
    for (int off = 1; off < 1024; off <<= 1) {
        int v = (tid >= off) ? sh[tid - off] : 0;
        __syncthreads();
        sh[tid] += v;
        __syncthreads();
    }
    int run = sh[tid] - s;                        // exclusive prefix
    for (int i = start; i < stop; i++) { g_rowptr[i] = run; run += g_deg[i] - 1; }
    if (tid == 1023) g_rowptr[N_NODES] = sh[1023];
}

__global__ void k_scatter(const int* __restrict__ src, const int* __restrict__ dst, int E) {
    int e = blockIdx.x * blockDim.x + threadIdx.x;
    if (e < E) {
        int d = dst[e];
        int pos = atomicAdd(&g_cursor[d], 1);
        g_col[g_rowptr[d] + pos] = src[e];
    }
}

// ---------------- dense GEMM: C[M,512] = A[M,512] @ W[512,512] --------------------
// 128x128 block tile, 8x8 thread tile, f32x2 packed accumulators.
#define BM 128
#define BN 128
#define BK 8
__global__ __launch_bounds__(256) void k_gemm(const float* __restrict__ A,
                                              const float* __restrict__ W,
                                              float* __restrict__ C) {
    __shared__ __align__(16) float As[BK][BM];
    __shared__ __align__(16) float Bs[BK][BN];
    int bx = blockIdx.x;            // n tile (0..3)
    int by = blockIdx.y;            // m tile (0..390)
    int tid = threadIdx.x;
    int tx = tid & 15, ty = tid >> 4;
    int row0 = by * BM;

    int aRow  = tid >> 1;           // 0..127
    int aCol4 = (tid & 1) * 4;      // 0 or 4
    int bRow  = tid >> 5;           // 0..7
    int bCol4 = (tid & 31) * 4;     // 0..124

    unsigned long long acc[8][4] = {};
    const float* Bp = W + bx * BN;

    for (int k0 = 0; k0 < DIM; k0 += BK) {
        int ar = row0 + aRow;
        float4 av = make_float4(0.f, 0.f, 0.f, 0.f);
        if (ar < N_NODES)
            av = *(const float4*)(A + (size_t)ar * DIM + k0 + aCol4);
        As[aCol4 + 0][aRow] = av.x;
        As[aCol4 + 1][aRow] = av.y;
        As[aCol4 + 2][aRow] = av.z;
        As[aCol4 + 3][aRow] = av.w;
        *(float4*)&Bs[bRow][bCol4] =
            *(const float4*)(Bp + (size_t)(k0 + bRow) * DIM + bCol4);
        __syncthreads();

#pragma unroll
        for (int kk = 0; kk < BK; kk++) {
            float4 a0 = *(const float4*)&As[kk][ty * 8];
            float4 a1 = *(const float4*)&As[kk][ty * 8 + 4];
            ulonglong2 b0 = *(const ulonglong2*)&Bs[kk][tx * 8];
            ulonglong2 b1 = *(const ulonglong2*)&Bs[kk][tx * 8 + 4];
            float av8[8] = {a0.x, a0.y, a0.z, a0.w, a1.x, a1.y, a1.z, a1.w};
#pragma unroll
            for (int i = 0; i < 8; i++) {
                unsigned long long ad = dup2(av8[i]);
                fma2(acc[i][0], ad, b0.x);
                fma2(acc[i][1], ad, b0.y);
                fma2(acc[i][2], ad, b1.x);
                fma2(acc[i][3], ad, b1.y);
            }
        }
        __syncthreads();
    }

    int colBase = bx * BN + tx * 8;
#pragma unroll
    for (int i = 0; i < 8; i++) {
        int r = row0 + ty * 8 + i;
        if (r < N_NODES) {
            float2 f0 = unpack2(acc[i][0]);
            float2 f1 = unpack2(acc[i][1]);
            float2 f2 = unpack2(acc[i][2]);
            float2 f3 = unpack2(acc[i][3]);
            *(float4*)(C + (size_t)r * DIM + colBase)     = make_float4(f0.x, f0.y, f1.x, f1.y);
            *(float4*)(C + (size_t)r * DIM + colBase + 4) = make_float4(f2.x, f2.y, f3.x, f3.y);
        }
    }
}

// ---------------- SpMM: out = D^-1/2 (A + I) D^-1/2 H + bias ----------------------
// one block (128 threads) per destination node; CSR neighbor list, no float atomics
__global__ __launch_bounds__(128) void k_spmm(const float* __restrict__ H,
                                              const float* __restrict__ bias,
                                              float* __restrict__ out) {
    int node = blockIdx.x;
    int tid  = threadIdx.x;
    float dd = g_dis[node];
    int beg = g_rowptr[node];
    int end = g_rowptr[node + 1];

    float4 hv = ((const float4*)(H + (size_t)node * DIM))[tid];
    float wSelf = dd * dd;
    float4 acc = make_float4(wSelf * hv.x, wSelf * hv.y, wSelf * hv.z, wSelf * hv.w);

    __shared__ int   s_nb[128];
    __shared__ float s_w[128];
    for (int c = beg; c < end; c += 128) {
        int cnt = min(128, end - c);
        if (tid < cnt) {
            int s = g_col[c + tid];
            s_nb[tid] = s;
            s_w[tid]  = g_dis[s] * dd;
        }
        __syncthreads();
#pragma unroll 2
        for (int j = 0; j < cnt; j++) {
            float ww = s_w[j];
            float4 v = ((const float4*)(H + (size_t)s_nb[j] * DIM))[tid];
            acc.x += ww * v.x; acc.y += ww * v.y;
            acc.z += ww * v.z; acc.w += ww * v.w;
        }
        __syncthreads();
    }
    float4 bv = ((const float4*)bias)[tid];
    acc.x += bv.x; acc.y += bv.y; acc.z += bv.z; acc.w += bv.w;
    ((float4*)(out + (size_t)node * DIM))[tid] = acc;
}

// ---------------- BatchNorm ------------------------------------------------------
__global__ void k_bn_zero() {
    int c = threadIdx.x;
    g_sum[c] = 0.f; g_sumsq[c] = 0.f;
}

#define BNR 128
__global__ __launch_bounds__(256) void k_bn_stats(const float* __restrict__ V) {
    int tid = threadIdx.x;             // 256 threads, 2 cols each
    int c0 = tid * 2;
    int r0 = blockIdx.x * BNR;
    int r1 = min(r0 + BNR, N_NODES);
    float s0 = 0.f, s1 = 0.f, q0 = 0.f, q1 = 0.f;
    for (int r = r0; r < r1; r++) {
        float2 v = *(const float2*)(V + (size_t)r * DIM + c0);
        s0 += v.x; q0 += v.x * v.x;
        s1 += v.y; q1 += v.y * v.y;
    }
    atomicAdd(&g_sum[c0], s0);     atomicAdd(&g_sumsq[c0], q0);
    atomicAdd(&g_sum[c0 + 1], s1); atomicAdd(&g_sumsq[c0 + 1], q1);
}

__global__ void k_bn_final(const float* __restrict__ gamma, const float* __restrict__ beta) {
    int c = threadIdx.x;
    const float invN = 1.f / (float)N_NODES;
    float mean = g_sum[c] * invN;
    float var  = fmaxf(g_sumsq[c] * invN - mean * mean, 0.f);
    float rstd = rsqrtf(var + 1e-5f);
    float sc = rstd * gamma[c];
    g_scale[c] = sc;
    g_shift[c] = beta[c] - mean * sc;
}

__global__ __launch_bounds__(256) void k_bn_apply_relu(const float* __restrict__ V,
                                                       float* __restrict__ X) {
    int idx = blockIdx.x * 256 + threadIdx.x;       // over N*DIM/4 float4s
    float4 v = ((const float4*)V)[idx];
    int c4 = idx & (DIM / 4 - 1);
    float4 sc = *(const float4*)&g_scale[c4 * 4];
    float4 sh = *(const float4*)&g_shift[c4 * 4];
    float4 o;
    o.x = fmaxf(fmaf(v.x, sc.x, sh.x), 0.f);
    o.y = fmaxf(fmaf(v.y, sc.y, sh.y), 0.f);
    o.z = fmaxf(fmaf(v.z, sc.z, sh.z), 0.f);
    o.w = fmaxf(fmaf(v.w, sc.w, sh.w), 0.f);
    ((float4*)X)[idx] = o;
}

// ---------------- JK-max + final GEMM (512->40) + log_softmax --------------------
// block: 256 threads = 64 row-groups x 4 output-quads; 256 rows/block
#define KC 32
__global__ __launch_bounds__(256) void k_jk_head(const float* __restrict__ Wf,
                                                 const float* __restrict__ bf,
                                                 float* __restrict__ out) {
    __shared__ float h_sh[256][KC + 1];      // +1 pad: conflict-free column reads
    __shared__ float wf_sh[KC][NOUT];
    int tid = threadIdx.x;
    int rg = tid >> 2;                       // 0..63
    int q  = tid & 3;                        // 10 outputs each
    int r0 = blockIdx.x * 256;

    float bfv[10];
#pragma unroll
    for (int o = 0; o < 10; o++) bfv[o] = bf[q * 10 + o];

    float acc[4][10];
#pragma unroll
    for (int i = 0; i < 4; i++)
#pragma unroll
        for (int o = 0; o < 10; o++) acc[i][o] = 0.f;

    for (int k0 = 0; k0 < DIM; k0 += KC) {
        // stage Wf chunk
        for (int i = tid; i < KC * NOUT; i += 256)
            wf_sh[i / NOUT][i % NOUT] = Wf[(size_t)(k0 + i / NOUT) * NOUT + (i % NOUT)];
        // stage h = max(x1,x2,x3) chunk: 256 rows x 32 cols
        for (int i = tid; i < 256 * (KC / 4); i += 256) {
            int rr = i >> 3;
            int kq = (i & 7) * 4;
            int grow = r0 + rr;
            float4 m = make_float4(0.f, 0.f, 0.f, 0.f);
            if (grow < N_NODES) {
                size_t off = (size_t)grow * DIM + k0 + kq;
                float4 a = *(const float4*)(g_x1 + off);
                float4 b = *(const float4*)(g_x2 + off);
                float4 c = *(const float4*)(g_x3 + off);
                m.x = fmaxf(fmaxf(a.x, b.x), c.x);
                m.y = fmaxf(fmaxf(a.y, b.y), c.y);
                m.z = fmaxf(fmaxf(a.z, b.z), c.z);
                m.w = fmaxf(fmaxf(a.w, b.w), c.w);
            }
            h_sh[rr][kq + 0] = m.x;
            h_sh[rr][kq + 1] = m.y;
            h_sh[rr][kq + 2] = m.z;
            h_sh[rr][kq + 3] = m.w;
        }
        __syncthreads();
        for (int k = 0; k < KC; k++) {
            float wv[10];
#pragma unroll
            for (int o = 0; o < 10; o++) wv[o] = wf_sh[k][q * 10 + o];
#pragma unroll
            for (int i = 0; i < 4; i++) {
                float hv = h_sh[rg * 4 + i][k];
#pragma unroll
                for (int o = 0; o < 10; o++) acc[i][o] += hv * wv[o];
            }
        }
        __syncthreads();
    }

    // per-row log_softmax: row owned by 4 consecutive lanes (q = 0..3)
#pragma unroll
    for (int i = 0; i < 4; i++) {
        float vbuf[10];
        float m = -3.4e38f;
#pragma unroll
        for (int o = 0; o < 10; o++) {
            float v = acc[i][o] + bfv[o];
            vbuf[o] = v;
            m = fmaxf(m, v);
        }
        m = fmaxf(m, __shfl_xor_sync(0xffffffffu, m, 1));
        m = fmaxf(m, __shfl_xor_sync(0xffffffffu, m, 2));
        float s = 0.f;
#pragma unroll
        for (int o = 0; o < 10; o++) s += expf(vbuf[o] - m);
        s += __shfl_xor_sync(0xffffffffu, s, 1);
        s += __shfl_xor_sync(0xffffffffu, s, 2);
        float lse = logf(s) + m;
        int row = r0 + rg * 4 + i;
        if (row < N_NODES) {
            float* op = out + (size_t)row * NOUT + q * 10;
#pragma unroll
            for (int o = 0; o < 10; o++) op[o] = vbuf[o] - lse;
        }
    }
}

// ---------------- launch ---------------------------------------------------------
extern "C" void kernel_launch(void* const* d_in, const int* in_sizes, int n_in,
                              void* d_out, int out_size) {
    const float* x   = (const float*)d_in[0];
    const int*   ei  = (const int*)d_in[1];
    const float* W1  = (const float*)d_in[2];
    const float* b1  = (const float*)d_in[3];
    const float* g1  = (const float*)d_in[4];
    const float* be1 = (const float*)d_in[5];
    const float* W2  = (const float*)d_in[6];
    const float* b2  = (const float*)d_in[7];
    const float* g2  = (const float*)d_in[8];
    const float* be2 = (const float*)d_in[9];
    const float* W3  = (const float*)d_in[10];
    const float* b3  = (const float*)d_in[11];
    const float* Wf  = (const float*)d_in[12];
    const float* bf  = (const float*)d_in[13];
    float* out = (float*)d_out;

    int E = in_sizes[1] / 2;
    const int* srcp = ei;
    const int* dstp = ei + E;

    void *p_tmp, *p_agg, *p_x1, *p_x2, *p_x3;
    cudaGetSymbolAddress(&p_tmp, g_tmp);
    cudaGetSymbolAddress(&p_agg, g_agg);
    cudaGetSymbolAddress(&p_x1, g_x1);
    cudaGetSymbolAddress(&p_x2, g_x2);
    cudaGetSymbolAddress(&p_x3, g_x3);
    float* tmp = (float*)p_tmp;
    float* agg = (float*)p_agg;
    float* x1  = (float*)p_x1;
    float* x2  = (float*)p_x2;
    float* x3  = (float*)p_x3;

    dim3 gemmGrid(DIM / BN, (N_NODES + BM - 1) / BM);
    int elemGrid = (N_NODES * DIM / 4) / 256;          // 25000
    int statGrid = (N_NODES + BNR - 1) / BNR;          // 391

    // graph preprocessing
    k_init<<<(N_NODES + 255) / 256, 256>>>();
    k_deg<<<(E + 255) / 256, 256>>>(dstp, E);
    k_dis<<<(N_NODES + 255) / 256, 256>>>();
    k_scan<<<1, 1024>>>();
    k_scatter<<<(E + 255) / 256, 256>>>(srcp, dstp, E);

    // layer 1
    k_gemm<<<gemmGrid, 256>>>(x, W1, tmp);
    k_spmm<<<N_NODES, 128>>>(tmp, b1, agg);
    k_bn_zero<<<1, DIM>>>();
    k_bn_stats<<<statGrid, 256>>>(agg);
    k_bn_final<<<1, DIM>>>(g1, be1);
    k_bn_apply_relu<<<elemGrid, 256>>>(agg, x1);

    // layer 2
    k_gemm<<<gemmGrid, 256>>>(x1, W2, tmp);
    k_spmm<<<N_NODES, 128>>>(tmp, b2, agg);
    k_bn_zero<<<1, DIM>>>();
    k_bn_stats<<<statGrid, 256>>>(agg);
    k_bn_final<<<1, DIM>>>(g2, be2);
    k_bn_apply_relu<<<elemGrid, 256>>>(agg, x2);

    // layer 3 (no BN / relu)
    k_gemm<<<gemmGrid, 256>>>(x2, W3, tmp);
    k_spmm<<<N_NODES, 128>>>(tmp, b3, x3);

    // JK max + classifier + log_softmax
    k_jk_head<<<(N_NODES + 255) / 256, 256>>>(Wf, bf, out);
}

// round 5
// speedup vs baseline: 1.8857x; 1.8857x over previous
#include <cuda_runtime.h>
#include <cuda_fp16.h>
#include <math.h>
#include <stdint.h>

#define N_NODES 50000
#define N_PAD   50048          // 391 * 128
#define DIM     512
#define NOUT    40
#define EMAX    800000

// ---------------- scratch (static device globals: allocation-free) ----------------
__device__ float g_tmp[(size_t)N_NODES * DIM];
__device__ float g_agg[(size_t)N_NODES * DIM];
__device__ float g_x1 [(size_t)N_NODES * DIM];
__device__ float g_x2 [(size_t)N_NODES * DIM];
__device__ float g_x3 [(size_t)N_NODES * DIM];
__device__ int   g_deg[N_NODES];
__device__ float g_dis[N_NODES];
__device__ int   g_rowptr[N_NODES + 1];
__device__ int   g_cursor[N_NODES];
__device__ int   g_col[EMAX];
__device__ float g_sum[DIM];
__device__ float g_sumsq[DIM];
__device__ float g_scale[DIM];
__device__ float g_shift[DIM];
// fp16 split buffers (stored as u16)
__device__ unsigned short g_ahi[(size_t)N_PAD * DIM];
__device__ unsigned short g_alo[(size_t)N_PAD * DIM];
__device__ unsigned short g_wthi[3 * DIM * DIM];
__device__ unsigned short g_wtlo[3 * DIM * DIM];

// ---------------- helpers ---------------------------------------------------------
__device__ __forceinline__ uint32_t smem_u32(const void* p) {
    uint32_t a;
    asm("{ .reg .u64 t; cvta.to.shared.u64 t, %1; cvt.u32.u64 %0, t; }" : "=r"(a) : "l"(p));
    return a;
}
__device__ __forceinline__ void cp16(uint32_t dst, const void* src) {
    asm volatile("cp.async.cg.shared.global [%0], [%1], 16;" :: "r"(dst), "l"(src) : "memory");
}
__device__ __forceinline__ unsigned pack2h(float a, float b) {
    __half2 h = __floats2half2_rn(a, b);
    return *(unsigned*)&h;
}

// ---------------- graph preprocessing -------------------------------------------
__global__ void k_init() {
    int i = blockIdx.x * blockDim.x + threadIdx.x;
    if (i < N_NODES) { g_deg[i] = 1; g_cursor[i] = 0; }
}
__global__ void k_deg(const int* __restrict__ dst, int E) {
    int e = blockIdx.x * blockDim.x + threadIdx.x;
    if (e < E) atomicAdd(&g_deg[dst[e]], 1);
}
__global__ void k_dis() {
    int i = blockIdx.x * blockDim.x + threadIdx.x;
    if (i < N_NODES) g_dis[i] = rsqrtf((float)g_deg[i]);
}
__global__ void k_scan() {
    __shared__ int sh[1024];
    int tid = threadIdx.x;
    const int per = (N_NODES + 1023) / 1024;
    int start = tid * per;
    int stop  = min(start + per, N_NODES);
    int s = 0;
    for (int i = start; i < stop; i++) s += g_deg[i] - 1;
    sh[tid] = s;
    __syncthreads();
    for (int off = 1; off < 1024; off <<= 1) {
        int v = (tid >= off) ? sh[tid - off] : 0;
        __syncthreads();
        sh[tid] += v;
        __syncthreads();
    }
    int run = sh[tid] - s;
    for (int i = start; i < stop; i++) { g_rowptr[i] = run; run += g_deg[i] - 1; }
    if (tid == 1023) g_rowptr[N_NODES] = sh[1023];
}
__global__ void k_scatter(const int* __restrict__ src, const int* __restrict__ dst, int E) {
    int e = blockIdx.x * blockDim.x + threadIdx.x;
    if (e < E) {
        int d = dst[e];
        int pos = atomicAdd(&g_cursor[d], 1);
        g_col[g_rowptr[d] + pos] = src[e];
    }
}

// ---------------- split kernels ---------------------------------------------------
// W -> Wt (transposed, K-major) hi/lo fp16, all three weight matrices
__global__ __launch_bounds__(256) void k_splitW(const float* __restrict__ W1,
                                                const float* __restrict__ W2,
                                                const float* __restrict__ W3) {
    int t = blockIdx.x * 256 + threadIdx.x;           // < 3*512*512
    int m = t >> 18;
    int i = t & 262143;
    int n = i >> 9, k = i & 511;
    const float* W = (m == 0) ? W1 : ((m == 1) ? W2 : W3);
    float v = W[k * DIM + n];
    __half h = __float2half_rn(v);
    float r = v - __half2float(h);
    g_wthi[t] = __half_as_ushort(h);
    g_wtlo[t] = __half_as_ushort(__float2half_rn(r));
}

// X (fp32, N_NODES rows) -> hi/lo fp16 with zero padding to N_PAD rows
__global__ __launch_bounds__(256) void k_split_x(const float* __restrict__ X) {
    int idx = blockIdx.x * 256 + threadIdx.x;         // < N_PAD*128 (float4 units)
    int row = idx >> 7;
    float4 v = make_float4(0.f, 0.f, 0.f, 0.f);
    if (row < N_NODES) v = ((const float4*)X)[idx];
    float h0 = __half2float(__float2half_rn(v.x));
    float h1 = __half2float(__float2half_rn(v.y));
    float h2 = __half2float(__float2half_rn(v.z));
    float h3 = __half2float(__float2half_rn(v.w));
    ((uint2*)g_ahi)[idx] = make_uint2(pack2h(v.x, v.y), pack2h(v.z, v.w));
    ((uint2*)g_alo)[idx] = make_uint2(pack2h(v.x - h0, v.y - h1), pack2h(v.z - h2, v.w - h3));
}

// ---------------- mma.sync GEMM: C[N_PAD,512] = A @ Wt^T (3-product fp16 split) ---
// CTA tile 128x128, warp tile 64x32 (2x4 warps), K-chunk 64, 2-stage cp.async.
// Arch-agnostic tensor core path (sm_80 mma.sync) — sm_100 plain target has no tcgen05.
#define STG_BYTES 32768                    // A 16KB + B 16KB per stage
#define GEMM_SMEM (2 * STG_BYTES)          // 65536

__global__ __launch_bounds__(256) void k_gemm_mma(
        const __half* __restrict__ Ahi, const __half* __restrict__ Alo,
        const __half* __restrict__ Bhi, const __half* __restrict__ Blo,
        float* __restrict__ C) {
    extern __shared__ char smem[];
    uint32_t sb = smem_u32(smem);
    int tid = threadIdx.x, wid = tid >> 5, lane = tid & 31;
    int row0 = blockIdx.y * 128;
    int n0   = blockIdx.x * 128;
    int warpM = (wid & 1) * 64;
    int warpN = (wid >> 1) * 32;

    float acc[4][4][4];
#pragma unroll
    for (int a = 0; a < 4; a++)
#pragma unroll
        for (int b = 0; b < 4; b++)
#pragma unroll
            for (int d = 0; d < 4; d++) acc[a][b][d] = 0.f;

    // chunk c: pass = c>>3 selects product, k0 = (c&7)*64
    auto issue = [&](int c) {
        int s = c & 1, pass = c >> 3, k0 = (c & 7) * 64;
        const __half* As = (pass < 2) ? Ahi : Alo;
        const __half* Bs = (pass == 1) ? Blo : Bhi;
        uint32_t aB = sb + s * STG_BYTES;
        uint32_t bB = aB + 16384;
#pragma unroll
        for (int i = 0; i < 8; i++) {
            int u = tid + i * 256;                    // 0..2047
            int r = (u & 1023) >> 3, ch = u & 7;
            uint32_t off = r * 128 + ch * 16;
            uint32_t sw = off ^ ((off >> 3) & 0x70);
            if (u < 1024)
                cp16(aB + sw, As + (size_t)(row0 + r) * DIM + k0 + ch * 8);
            else
                cp16(bB + sw, Bs + (size_t)(n0 + r) * DIM + k0 + ch * 8);
        }
        asm volatile("cp.async.commit_group;" ::: "memory");
    };

    issue(0);
    for (int c = 0; c < 24; c++) {
        if (c + 1 < 24) {
            issue(c + 1);
            asm volatile("cp.async.wait_group 1;" ::: "memory");
        } else {
            asm volatile("cp.async.wait_group 0;" ::: "memory");
        }
        __syncthreads();

        uint32_t aS = sb + (c & 1) * STG_BYTES;
        uint32_t bS = aS + 16384;
#pragma unroll
        for (int ks = 0; ks < 4; ks++) {
            uint32_t af[4][4];
#pragma unroll
            for (int mf = 0; mf < 4; mf++) {
                int row = warpM + mf * 16 + (lane & 15);
                uint32_t off = row * 128 + ks * 32 + ((lane >> 4) << 4);
                uint32_t ad = aS + (off ^ ((off >> 3) & 0x70));
                asm volatile("ldmatrix.sync.aligned.m8n8.x4.shared.b16 {%0,%1,%2,%3}, [%4];"
                             : "=r"(af[mf][0]), "=r"(af[mf][1]), "=r"(af[mf][2]), "=r"(af[mf][3])
                             : "r"(ad));
            }
            uint32_t bf[4][2];
#pragma unroll
            for (int p = 0; p < 2; p++) {
                int row = warpN + p * 16 + (lane & 7) + ((lane >> 4) << 3);
                uint32_t off = row * 128 + ks * 32 + (((lane >> 3) & 1) << 4);
                uint32_t ad = bS + (off ^ ((off >> 3) & 0x70));
                uint32_t r0, r1, r2, r3;
                asm volatile("ldmatrix.sync.aligned.m8n8.x4.shared.b16 {%0,%1,%2,%3}, [%4];"
                             : "=r"(r0), "=r"(r1), "=r"(r2), "=r"(r3) : "r"(ad));
                bf[p * 2][0] = r0; bf[p * 2][1] = r1;
                bf[p * 2 + 1][0] = r2; bf[p * 2 + 1][1] = r3;
            }
#pragma unroll
            for (int mf = 0; mf < 4; mf++)
#pragma unroll
                for (int nf = 0; nf < 4; nf++) {
                    asm volatile(
                        "mma.sync.aligned.m16n8k16.row.col.f32.f16.f16.f32 "
                        "{%0,%1,%2,%3}, {%4,%5,%6,%7}, {%8,%9}, {%0,%1,%2,%3};"
                        : "+f"(acc[mf][nf][0]), "+f"(acc[mf][nf][1]),
                          "+f"(acc[mf][nf][2]), "+f"(acc[mf][nf][3])
                        : "r"(af[mf][0]), "r"(af[mf][1]), "r"(af[mf][2]), "r"(af[mf][3]),
                          "r"(bf[nf][0]), "r"(bf[nf][1]));
                }
        }
        __syncthreads();
    }

    // epilogue: d0,d1 -> (row, col..col+1); d2,d3 -> (row+8, ...)
#pragma unroll
    for (int mf = 0; mf < 4; mf++)
#pragma unroll
        for (int nf = 0; nf < 4; nf++) {
            int rg = row0 + warpM + mf * 16 + (lane >> 2);
            int cg = n0 + warpN + nf * 8 + (lane & 3) * 2;
            if (rg < N_NODES)
                *(float2*)(C + (size_t)rg * DIM + cg) =
                    make_float2(acc[mf][nf][0], acc[mf][nf][1]);
            if (rg + 8 < N_NODES)
                *(float2*)(C + (size_t)(rg + 8) * DIM + cg) =
                    make_float2(acc[mf][nf][2], acc[mf][nf][3]);
        }
}

// ---------------- SpMM: out = D^-1/2 (A + I) D^-1/2 H + bias ----------------------
__global__ __launch_bounds__(128) void k_spmm(const float* __restrict__ H,
                                              const float* __restrict__ bias,
                                              float* __restrict__ out) {
    int node = blockIdx.x;
    int tid  = threadIdx.x;
    float dd = g_dis[node];
    int beg = g_rowptr[node];
    int end = g_rowptr[node + 1];

    float4 hv = ((const float4*)(H + (size_t)node * DIM))[tid];
    float wSelf = dd * dd;
    float4 acc = make_float4(wSelf * hv.x, wSelf * hv.y, wSelf * hv.z, wSelf * hv.w);

    __shared__ int   s_nb[128];
    __shared__ float s_w[128];
    for (int c = beg; c < end; c += 128) {
        int cnt = min(128, end - c);
        if (tid < cnt) {
            int s = g_col[c + tid];
            s_nb[tid] = s;
            s_w[tid]  = g_dis[s] * dd;
        }
        __syncthreads();
#pragma unroll 2
        for (int j = 0; j < cnt; j++) {
            float ww = s_w[j];
            float4 v = ((const float4*)(H + (size_t)s_nb[j] * DIM))[tid];
            acc.x += ww * v.x; acc.y += ww * v.y;
            acc.z += ww * v.z; acc.w += ww * v.w;
        }
        __syncthreads();
    }
    float4 bv = ((const float4*)bias)[tid];
    acc.x += bv.x; acc.y += bv.y; acc.z += bv.z; acc.w += bv.w;
    ((float4*)(out + (size_t)node * DIM))[tid] = acc;
}

// ---------------- BatchNorm ------------------------------------------------------
__global__ void k_bn_zero() {
    int c = threadIdx.x;
    g_sum[c] = 0.f; g_sumsq[c] = 0.f;
}
#define BNR 128
__global__ __launch_bounds__(256) void k_bn_stats(const float* __restrict__ V) {
    int tid = threadIdx.x;
    int c0 = tid * 2;
    int r0 = blockIdx.x * BNR;
    int r1 = min(r0 + BNR, N_NODES);
    float s0 = 0.f, s1 = 0.f, q0 = 0.f, q1 = 0.f;
    for (int r = r0; r < r1; r++) {
        float2 v = *(const float2*)(V + (size_t)r * DIM + c0);
        s0 += v.x; q0 += v.x * v.x;
        s1 += v.y; q1 += v.y * v.y;
    }
    atomicAdd(&g_sum[c0], s0);     atomicAdd(&g_sumsq[c0], q0);
    atomicAdd(&g_sum[c0 + 1], s1); atomicAdd(&g_sumsq[c0 + 1], q1);
}
__global__ void k_bn_final(const float* __restrict__ gamma, const float* __restrict__ beta) {
    int c = threadIdx.x;
    const float invN = 1.f / (float)N_NODES;
    float mean = g_sum[c] * invN;
    float var  = fmaxf(g_sumsq[c] * invN - mean * mean, 0.f);
    float rstd = rsqrtf(var + 1e-5f);
    float sc = rstd * gamma[c];
    g_scale[c] = sc;
    g_shift[c] = beta[c] - mean * sc;
}
// BN apply + relu + fused fp16 hi/lo split (pad rows of g_ahi/g_alo stay zero)
__global__ __launch_bounds__(256) void k_bn_apply_relu_split(const float* __restrict__ V,
                                                             float* __restrict__ X) {
    int idx = blockIdx.x * 256 + threadIdx.x;         // over N_NODES*128 float4s
    float4 v = ((const float4*)V)[idx];
    int c4 = idx & (DIM / 4 - 1);
    float4 sc = *(const float4*)&g_scale[c4 * 4];
    float4 sh = *(const float4*)&g_shift[c4 * 4];
    float4 o;
    o.x = fmaxf(fmaf(v.x, sc.x, sh.x), 0.f);
    o.y = fmaxf(fmaf(v.y, sc.y, sh.y), 0.f);
    o.z = fmaxf(fmaf(v.z, sc.z, sh.z), 0.f);
    o.w = fmaxf(fmaf(v.w, sc.w, sh.w), 0.f);
    ((float4*)X)[idx] = o;
    float h0 = __half2float(__float2half_rn(o.x));
    float h1 = __half2float(__float2half_rn(o.y));
    float h2 = __half2float(__float2half_rn(o.z));
    float h3 = __half2float(__float2half_rn(o.w));
    ((uint2*)g_ahi)[idx] = make_uint2(pack2h(o.x, o.y), pack2h(o.z, o.w));
    ((uint2*)g_alo)[idx] = make_uint2(pack2h(o.x - h0, o.y - h1), pack2h(o.z - h2, o.w - h3));
}

// ---------------- JK-max + final GEMM (512->40) + log_softmax --------------------
#define KC 32
__global__ __launch_bounds__(256) void k_jk_head(const float* __restrict__ Wf,
                                                 const float* __restrict__ bf,
                                                 float* __restrict__ out) {
    __shared__ float h_sh[256][KC + 1];
    __shared__ float wf_sh[KC][NOUT];
    int tid = threadIdx.x;
    int rg = tid >> 2;
    int q  = tid & 3;
    int r0 = blockIdx.x * 256;

    float bfv[10];
#pragma unroll
    for (int o = 0; o < 10; o++) bfv[o] = bf[q * 10 + o];

    float acc[4][10];
#pragma unroll
    for (int i = 0; i < 4; i++)
#pragma unroll
        for (int o = 0; o < 10; o++) acc[i][o] = 0.f;

    for (int k0 = 0; k0 < DIM; k0 += KC) {
        for (int i = tid; i < KC * NOUT; i += 256)
            wf_sh[i / NOUT][i % NOUT] = Wf[(size_t)(k0 + i / NOUT) * NOUT + (i % NOUT)];
        for (int i = tid; i < 256 * (KC / 4); i += 256) {
            int rr = i >> 3;
            int kq = (i & 7) * 4;
            int grow = r0 + rr;
            float4 m = make_float4(0.f, 0.f, 0.f, 0.f);
            if (grow < N_NODES) {
                size_t off = (size_t)grow * DIM + k0 + kq;
                float4 a = *(const float4*)(g_x1 + off);
                float4 b = *(const float4*)(g_x2 + off);
                float4 c = *(const float4*)(g_x3 + off);
                m.x = fmaxf(fmaxf(a.x, b.x), c.x);
                m.y = fmaxf(fmaxf(a.y, b.y), c.y);
                m.z = fmaxf(fmaxf(a.z, b.z), c.z);
                m.w = fmaxf(fmaxf(a.w, b.w), c.w);
            }
            h_sh[rr][kq + 0] = m.x;
            h_sh[rr][kq + 1] = m.y;
            h_sh[rr][kq + 2] = m.z;
            h_sh[rr][kq + 3] = m.w;
        }
        __syncthreads();
        for (int k = 0; k < KC; k++) {
            float wv[10];
#pragma unroll
            for (int o = 0; o < 10; o++) wv[o] = wf_sh[k][q * 10 + o];
#pragma unroll
            for (int i = 0; i < 4; i++) {
                float hv = h_sh[rg * 4 + i][k];
#pragma unroll
                for (int o = 0; o < 10; o++) acc[i][o] += hv * wv[o];
            }
        }
        __syncthreads();
    }

#pragma unroll
    for (int i = 0; i < 4; i++) {
        float vbuf[10];
        float m = -3.4e38f;
#pragma unroll
        for (int o = 0; o < 10; o++) {
            float v = acc[i][o] + bfv[o];
            vbuf[o] = v;
            m = fmaxf(m, v);
        }
        m = fmaxf(m, __shfl_xor_sync(0xffffffffu, m, 1));
        m = fmaxf(m, __shfl_xor_sync(0xffffffffu, m, 2));
        float s = 0.f;
#pragma unroll
        for (int o = 0; o < 10; o++) s += expf(vbuf[o] - m);
        s += __shfl_xor_sync(0xffffffffu, s, 1);
        s += __shfl_xor_sync(0xffffffffu, s, 2);
        float lse = logf(s) + m;
        int row = r0 + rg * 4 + i;
        if (row < N_NODES) {
            float* op = out + (size_t)row * NOUT + q * 10;
#pragma unroll
            for (int o = 0; o < 10; o++) op[o] = vbuf[o] - lse;
        }
    }
}

// ---------------- launch ---------------------------------------------------------
extern "C" void kernel_launch(void* const* d_in, const int* in_sizes, int n_in,
                              void* d_out, int out_size) {
    const float* x   = (const float*)d_in[0];
    const int*   ei  = (const int*)d_in[1];
    const float* W1  = (const float*)d_in[2];
    const float* b1  = (const float*)d_in[3];
    const float* g1  = (const float*)d_in[4];
    const float* be1 = (const float*)d_in[5];
    const float* W2  = (const float*)d_in[6];
    const float* b2  = (const float*)d_in[7];
    const float* g2  = (const float*)d_in[8];
    const float* be2 = (const float*)d_in[9];
    const float* W3  = (const float*)d_in[10];
    const float* b3  = (const float*)d_in[11];
    const float* Wf  = (const float*)d_in[12];
    const float* bf  = (const float*)d_in[13];
    float* out = (float*)d_out;

    int E = in_sizes[1] / 2;
    const int* srcp = ei;
    const int* dstp = ei + E;

    void *p_tmp, *p_agg, *p_x1, *p_x2, *p_x3, *p_ahi, *p_alo, *p_whi, *p_wlo;
    cudaGetSymbolAddress(&p_tmp, g_tmp);
    cudaGetSymbolAddress(&p_agg, g_agg);
    cudaGetSymbolAddress(&p_x1, g_x1);
    cudaGetSymbolAddress(&p_x2, g_x2);
    cudaGetSymbolAddress(&p_x3, g_x3);
    cudaGetSymbolAddress(&p_ahi, g_ahi);
    cudaGetSymbolAddress(&p_alo, g_alo);
    cudaGetSymbolAddress(&p_whi, g_wthi);
    cudaGetSymbolAddress(&p_wlo, g_wtlo);
    float* tmp = (float*)p_tmp;
    float* agg = (float*)p_agg;
    float* x1  = (float*)p_x1;
    float* x2  = (float*)p_x2;
    float* x3  = (float*)p_x3;
    const __half* ahi = (const __half*)p_ahi;
    const __half* alo = (const __half*)p_alo;
    const __half* whi = (const __half*)p_whi;
    const __half* wlo = (const __half*)p_wlo;

    cudaFuncSetAttribute(k_gemm_mma, cudaFuncAttributeMaxDynamicSharedMemorySize, GEMM_SMEM);

    dim3 gemmGrid(4, N_PAD / 128);                     // 4 N-tiles x 391 M-tiles
    int elemGrid = (N_NODES * DIM / 4) / 256;          // 25000
    int padGrid  = (N_PAD * DIM / 4) / 256;            // 25024
    int statGrid = (N_NODES + BNR - 1) / BNR;

    // graph preprocessing
    k_init<<<(N_NODES + 255) / 256, 256>>>();
    k_deg<<<(E + 255) / 256, 256>>>(dstp, E);
    k_dis<<<(N_NODES + 255) / 256, 256>>>();
    k_scan<<<1, 1024>>>();
    k_scatter<<<(E + 255) / 256, 256>>>(srcp, dstp, E);

    // weight splits (all 3 layers) + input split
    k_splitW<<<(3 * DIM * DIM) / 256, 256>>>(W1, W2, W3);
    k_split_x<<<padGrid, 256>>>(x);

    // layer 1
    k_gemm_mma<<<gemmGrid, 256, GEMM_SMEM>>>(ahi, alo, whi, wlo, tmp);
    k_spmm<<<N_NODES, 128>>>(tmp, b1, agg);
    k_bn_zero<<<1, DIM>>>();
    k_bn_stats<<<statGrid, 256>>>(agg);
    k_bn_final<<<1, DIM>>>(g1, be1);
    k_bn_apply_relu_split<<<elemGrid, 256>>>(agg, x1);

    // layer 2
    k_gemm_mma<<<gemmGrid, 256, GEMM_SMEM>>>(ahi, alo, whi + DIM * DIM, wlo + DIM * DIM, tmp);
    k_spmm<<<N_NODES, 128>>>(tmp, b2, agg);
    k_bn_zero<<<1, DIM>>>();
    k_bn_stats<<<statGrid, 256>>>(agg);
    k_bn_final<<<1, DIM>>>(g2, be2);
    k_bn_apply_relu_split<<<elemGrid, 256>>>(agg, x2);

    // layer 3 (no BN / relu)
    k_gemm_mma<<<gemmGrid, 256, GEMM_SMEM>>>(ahi, alo, whi + 2 * DIM * DIM, wlo + 2 * DIM * DIM, tmp);
    k_spmm<<<N_NODES, 128>>>(tmp, b3, x3);

    // JK max + classifier + log_softmax
    k_jk_head<<<(N_NODES + 255) / 256, 256>>>(Wf, bf, out);
}